// round 4
// baseline (speedup 1.0000x reference)
#include <cuda_runtime.h>

// Problem constants (shapes fixed by the dataset)
#define BB    1024          // batch
#define SSEQ  2048          // sequence length
#define FFEAT 9             // input features (NO+1)
#define NOUT  8             // output channels
#define LBK   3             // lookback
#define DD    11            // NO+3 (ln1 width)
#define UU    256           // hidden U
#define H1N   512           // 2U
#define TOUTN 2044          // S-1-LBK output steps
#define RR    8             // batch rows per block
#define NT    512           // threads per block
#define NBLK  128           // BB / RR
#define LN_EPS 1e-3f

typedef unsigned long long u64;

// ---- TF32 operand rounding --------------------------------------------------
// The JAX reference lowers f32 dot_generals to TF32 tensor-core GEMMs (JAX GPU
// default matmul precision). tf32 x tf32 products are EXACT in fp32, so
// rounding both operands of every dot with cvt.rna matches the reference's
// per-element products bit-for-bit; only accumulation-order noise remains.
__device__ __forceinline__ float tf32r(float a) {
    unsigned r;
    asm("cvt.rna.tf32.f32 %0, %1;" : "=r"(r) : "f"(a));
    return __uint_as_float(r);
}

// TF32-rounded weight copies (filled by a pre-kernel each launch; device
// globals, so no allocation rules are violated).
__device__ float rw_ew1[LBK * DD * H1N];
__device__ float rw_ew2[H1N * UU];
__device__ float rw_uw [UU * UU];
__device__ float rw_bw [UU];
__device__ float rw_dw1[(UU + 1) * H1N];
__device__ float rw_dw2[H1N * NOUT];

__global__ void round_weights_kernel(const float* __restrict__ ew1,
                                     const float* __restrict__ ew2,
                                     const float* __restrict__ uw,
                                     const float* __restrict__ bw,
                                     const float* __restrict__ dw1,
                                     const float* __restrict__ dw2)
{
    int i = blockIdx.x * blockDim.x + threadIdx.x;
    int stride = gridDim.x * blockDim.x;
    for (int k = i; k < LBK * DD * H1N; k += stride) rw_ew1[k] = tf32r(ew1[k]);
    for (int k = i; k < H1N * UU;      k += stride) rw_ew2[k] = tf32r(ew2[k]);
    for (int k = i; k < UU * UU;       k += stride) rw_uw[k]  = tf32r(uw[k]);
    for (int k = i; k < UU;            k += stride) rw_bw[k]  = tf32r(bw[k]);
    for (int k = i; k < (UU+1) * H1N;  k += stride) rw_dw1[k] = tf32r(dw1[k]);
    for (int k = i; k < H1N * NOUT;    k += stride) rw_dw2[k] = tf32r(dw2[k]);
}

// ---- packed fp32x2 helpers (Blackwell f32x2 pipe: 2 MACs per FFMA issue) ----
__device__ __forceinline__ u64 pack2(float lo, float hi) {
    u64 r; asm("mov.b64 %0, {%1,%2};" : "=l"(r) : "f"(lo), "f"(hi)); return r;
}
__device__ __forceinline__ void unpack2(u64 v, float& lo, float& hi) {
    asm("mov.b64 {%0,%1}, %2;" : "=f"(lo), "=f"(hi) : "l"(v));
}
__device__ __forceinline__ void fma2(u64& d, u64 a, u64 b) {
    asm("fma.rn.f32x2 %0, %1, %2, %0;" : "+l"(d) : "l"(a), "l"(b));
}
__device__ __forceinline__ u64 add2(u64 a, u64 b) {
    u64 r; asm("add.rn.f32x2 %0, %1, %2;" : "=l"(r) : "l"(a), "l"(b)); return r;
}

// ---- accurate math, immune to fast-math lowering ----------------------------
__device__ __forceinline__ float rcp_acc(float d) {
    float r0; asm("rcp.approx.f32 %0, %1;" : "=f"(r0) : "f"(d));
    float e = fmaf(-d, r0, 1.0f);
    return fmaf(r0, e, r0);
}

__device__ __forceinline__ float rsqrt_acc(float a) {
    float r; asm("rsqrt.approx.f32 %0, %1;" : "=f"(r) : "f"(a));
    float h = 0.5f * a;
    float e = fmaf(-h, r * r, 0.5f);
    return fmaf(r, e, r);
}

__device__ __forceinline__ float tanh_acc(float x) {
    float ax = fabsf(x);
    if (ax < 0.25f) {
        float x2 = x * x;
        float p = fmaf(x2, 2.1869489e-2f, -5.3968254e-2f);
        p = fmaf(x2, p, 1.3333334e-1f);
        p = fmaf(x2, p, -3.3333334e-1f);
        return fmaf(x * x2, p, x);
    }
    if (ax > 9.1f) return copysignf(1.0f, x);
    float t = ax * 2.88539008177793f;
    float n = rintf(t);
    float f = t - n;
    float p = fmaf(f, 1.5252734e-5f, 1.5403530e-4f);
    p = fmaf(f, p, 1.3333558e-3f);
    p = fmaf(f, p, 9.6181292e-3f);
    p = fmaf(f, p, 5.5504109e-2f);
    p = fmaf(f, p, 2.4022651e-1f);
    p = fmaf(f, p, 6.9314718e-1f);
    p = fmaf(f, p, 1.0f);
    float sc = __int_as_float(((int)n + 127) << 23);
    float q = p * sc;
    float r = rcp_acc(q + 1.0f);
    return copysignf(fmaf(-2.0f, r, 1.0f), x);
}

// Shared memory: activations kept transposed [feature][row] so the GEMV k-loops
// do broadcast LDS.128 reads (conflict-free).
struct __align__(16) SmemT {
    float4 xT[LBK * DD][2];     // x33 transposed  [k][r0..3],[r4..7]  (tf32)
    float4 h1T[H1N][2];         // tanh(enc1) transposed               (tf32)
    float4 hT[UU][2];           // enc2 out transposed                 (tf32)
    float4 combT[UU + 1][2];    // [st, ect] transposed                (tf32)
    u64    redU[UU][4];         // split-K reduction scratch (packed pairs)
    float  hh[RR][UU + 8];      // enc2 out row-major (beta dot)       (tf32)
    float  ss[RR][UU + 8];      // upd out row-major (LN2 input, fp32)
    float  gg[RR][H1N + 8];     // tanh(dec1) row-major (dec2 input)   (tf32)
    float  redF[NT];            // dec2 reduction scratch
    float  win[RR][LBK][NOUT];  // rolling window (full fp32)
    float  yS[RR][NOUT];        // current step output (full fp32)
    float  uS[RR][2];           // forced update values
};

__global__ __launch_bounds__(NT, 1)
void dps_kernel(const float* __restrict__ inp,
                const float* __restrict__ g1,  const float* __restrict__ be1,
                const float* __restrict__ eb1, const float* __restrict__ eb2,
                const float* __restrict__ ub,
                const float* __restrict__ g2,  const float* __restrict__ be2,
                const float* __restrict__ db1, const float* __restrict__ db2,
                const int* __restrict__ fixp,
                float* __restrict__ out)
{
    extern __shared__ char smraw[];
    SmemT* sm = reinterpret_cast<SmemT*>(smraw);
    const int tid = threadIdx.x;
    const int b0  = blockIdx.x * RR;

    const int f0 = fixp[0];
    const int f1 = fixp[1];

    // init rolling window: win = inputs[:, 0:3, 1:9]
    for (int idx = tid; idx < RR * LBK * NOUT; idx += NT) {
        int r = idx / (LBK * NOUT);
        int rem = idx % (LBK * NOUT);
        int t = rem / NOUT, c = rem % NOUT;
        sm->win[r][t][c] = inp[(size_t)(b0 + r) * SSEQ * FFEAT + t * FFEAT + 1 + c];
    }
    __syncthreads();

    float* xTf    = reinterpret_cast<float*>(sm->xT);
    float* combTf = reinterpret_cast<float*>(sm->combT);

    for (int i = LBK; i <= SSEQ - 2; ++i) {
        // -------- phase 0: build x (lc ++ window), LN1, write transposed (tf32)
        if (tid < RR * LBK) {
            int r = tid / LBK, t = tid % LBK;
            int tp = i - LBK + t;
            const float* rowp = inp + (size_t)(b0 + r) * SSEQ * FFEAT;
            float L  = rowp[tp * FFEAT];
            float Lm = (tp > 0) ? rowp[(tp - 1) * FFEAT] : 0.0f;
            float v[DD];
            v[0] = L;                               // loading
            v[1] = L;                               // cumsum over size-1 axis == loading
            v[2] = (tp > 0) ? (L - Lm) : 0.0f;      // diff; PADDED TO ZERO at t'=0
            #pragma unroll
            for (int c = 0; c < NOUT; ++c) v[3 + c] = sm->win[r][t][c];
            float s = 0.f;
            #pragma unroll
            for (int j = 0; j < DD; ++j) s += v[j];
            float m = s * (1.0f / DD);
            float q = 0.f;
            #pragma unroll
            for (int j = 0; j < DD; ++j) { float d = v[j] - m; q = fmaf(d, d, q); }
            float invs = rsqrt_acc(q * (1.0f / DD) + LN_EPS);
            #pragma unroll
            for (int j = 0; j < DD; ++j) {
                int k = t * DD + j;
                xTf[k * 8 + r] = tf32r(fmaf((v[j] - m) * invs, g1[j], be1[j]));
            }
        } else if (tid >= 32 && tid < 32 + RR * 2) {
            int qq = tid - 32;
            int r = qq >> 1, j = qq & 1;
            int ch = 1 + (j ? f1 : f0);
            sm->uS[r][j] = inp[(size_t)(b0 + r) * SSEQ * FFEAT + (size_t)(i + 1) * FFEAT + ch];
        }
        __syncthreads();

        // -------- L1: h1 = tanh(x33 @ ew1 + eb1)   K=33, N=512
        {
            const int n = tid;
            u64 a0 = 0, a1 = 0, a2 = 0, a3 = 0;
            #pragma unroll 3
            for (int k = 0; k < LBK * DD; ++k) {
                float w = rw_ew1[k * H1N + n];
                u64 ww = pack2(w, w);
                ulonglong2 x01 = *reinterpret_cast<const ulonglong2*>(&sm->xT[k][0]);
                ulonglong2 x23 = *reinterpret_cast<const ulonglong2*>(&sm->xT[k][1]);
                fma2(a0, x01.x, ww); fma2(a1, x01.y, ww);
                fma2(a2, x23.x, ww); fma2(a3, x23.y, ww);
            }
            float v[8];
            unpack2(a0, v[0], v[1]); unpack2(a1, v[2], v[3]);
            unpack2(a2, v[4], v[5]); unpack2(a3, v[6], v[7]);
            float b = eb1[n];
            float4 o0, o1;
            o0.x = tf32r(tanh_acc(v[0] + b)); o0.y = tf32r(tanh_acc(v[1] + b));
            o0.z = tf32r(tanh_acc(v[2] + b)); o0.w = tf32r(tanh_acc(v[3] + b));
            o1.x = tf32r(tanh_acc(v[4] + b)); o1.y = tf32r(tanh_acc(v[5] + b));
            o1.z = tf32r(tanh_acc(v[6] + b)); o1.w = tf32r(tanh_acc(v[7] + b));
            sm->h1T[n][0] = o0; sm->h1T[n][1] = o1;
        }
        __syncthreads();

        // -------- L2: h = h1 @ ew2 + eb2   K=512 (split 2), N=256
        {
            const int n    = tid & (UU - 1);
            const int half = tid >> 8;
            u64 a0 = 0, a1 = 0, a2 = 0, a3 = 0;
            const int k0 = half << 8;
            #pragma unroll 8
            for (int kk = 0; kk < 256; ++kk) {
                int k = k0 + kk;
                float w = rw_ew2[k * UU + n];
                u64 ww = pack2(w, w);
                ulonglong2 x01 = *reinterpret_cast<const ulonglong2*>(&sm->h1T[k][0]);
                ulonglong2 x23 = *reinterpret_cast<const ulonglong2*>(&sm->h1T[k][1]);
                fma2(a0, x01.x, ww); fma2(a1, x01.y, ww);
                fma2(a2, x23.x, ww); fma2(a3, x23.y, ww);
            }
            if (half) {
                sm->redU[n][0] = a0; sm->redU[n][1] = a1;
                sm->redU[n][2] = a2; sm->redU[n][3] = a3;
            }
            __syncthreads();
            if (!half) {
                a0 = add2(a0, sm->redU[n][0]); a1 = add2(a1, sm->redU[n][1]);
                a2 = add2(a2, sm->redU[n][2]); a3 = add2(a3, sm->redU[n][3]);
                float v[8];
                unpack2(a0, v[0], v[1]); unpack2(a1, v[2], v[3]);
                unpack2(a2, v[4], v[5]); unpack2(a3, v[6], v[7]);
                float b = eb2[n];
                #pragma unroll
                for (int r = 0; r < 8; ++r) v[r] = tf32r(v[r] + b);
                sm->hT[n][0] = make_float4(v[0], v[1], v[2], v[3]);
                sm->hT[n][1] = make_float4(v[4], v[5], v[6], v[7]);
                #pragma unroll
                for (int r = 0; r < 8; ++r) sm->hh[r][n] = v[r];
            }
        }
        __syncthreads();

        // -------- L3: s = h @ uw + ub   K=256 (split 2), N=256 -> ss (fp32)
        {
            const int n    = tid & (UU - 1);
            const int half = tid >> 8;
            u64 a0 = 0, a1 = 0, a2 = 0, a3 = 0;
            const int k0 = half << 7;
            #pragma unroll 8
            for (int kk = 0; kk < 128; ++kk) {
                int k = k0 + kk;
                float w = rw_uw[k * UU + n];
                u64 ww = pack2(w, w);
                ulonglong2 x01 = *reinterpret_cast<const ulonglong2*>(&sm->hT[k][0]);
                ulonglong2 x23 = *reinterpret_cast<const ulonglong2*>(&sm->hT[k][1]);
                fma2(a0, x01.x, ww); fma2(a1, x01.y, ww);
                fma2(a2, x23.x, ww); fma2(a3, x23.y, ww);
            }
            if (half) {
                sm->redU[n][0] = a0; sm->redU[n][1] = a1;
                sm->redU[n][2] = a2; sm->redU[n][3] = a3;
            }
            __syncthreads();
            if (!half) {
                a0 = add2(a0, sm->redU[n][0]); a1 = add2(a1, sm->redU[n][1]);
                a2 = add2(a2, sm->redU[n][2]); a3 = add2(a3, sm->redU[n][3]);
                float v[8];
                unpack2(a0, v[0], v[1]); unpack2(a1, v[2], v[3]);
                unpack2(a2, v[4], v[5]); unpack2(a3, v[6], v[7]);
                float b = ub[n];
                #pragma unroll
                for (int r = 0; r < 8; ++r) sm->ss[r][n] = v[r] + b;
            }
        }
        __syncthreads();

        // -------- LN2 (two-pass variance) + ect -> combT (warp w handles row w)
        if (tid < 256) {
            int r = tid >> 5, lane = tid & 31;
            float s = 0.f, e = 0.f;
            float vv[8];
            #pragma unroll
            for (int j = 0; j < 8; ++j) {
                int n = lane + (j << 5);
                float v = sm->ss[r][n];
                vv[j] = v;
                s += v;
                e = fmaf(sm->hh[r][n], rw_bw[n], e);
            }
            #pragma unroll
            for (int o = 16; o > 0; o >>= 1) {
                s += __shfl_xor_sync(0xffffffffu, s, o);
                e += __shfl_xor_sync(0xffffffffu, e, o);
            }
            float m = s * (1.0f / UU);
            float q = 0.f;
            #pragma unroll
            for (int j = 0; j < 8; ++j) { float d = vv[j] - m; q = fmaf(d, d, q); }
            #pragma unroll
            for (int o = 16; o > 0; o >>= 1)
                q += __shfl_xor_sync(0xffffffffu, q, o);
            float invs = rsqrt_acc(q * (1.0f / UU) + LN_EPS);
            #pragma unroll
            for (int j = 0; j < 8; ++j) {
                int n = lane + (j << 5);
                combTf[n * 8 + r] = tf32r(fmaf((vv[j] - m) * invs, g2[n], be2[n]));
            }
            if (lane == 0) combTf[UU * 8 + r] = tf32r(e);   // ect at comb index 256
        }
        __syncthreads();

        // -------- dec1: g = tanh(comb @ dw1 + db1)   K=257, N=512
        {
            const int n = tid;
            u64 a0 = 0, a1 = 0, a2 = 0, a3 = 0;
            #pragma unroll 8
            for (int k = 0; k < UU + 1; ++k) {
                float w = rw_dw1[k * H1N + n];
                u64 ww = pack2(w, w);
                ulonglong2 x01 = *reinterpret_cast<const ulonglong2*>(&sm->combT[k][0]);
                ulonglong2 x23 = *reinterpret_cast<const ulonglong2*>(&sm->combT[k][1]);
                fma2(a0, x01.x, ww); fma2(a1, x01.y, ww);
                fma2(a2, x23.x, ww); fma2(a3, x23.y, ww);
            }
            float v[8];
            unpack2(a0, v[0], v[1]); unpack2(a1, v[2], v[3]);
            unpack2(a2, v[4], v[5]); unpack2(a3, v[6], v[7]);
            float b = db1[n];
            #pragma unroll
            for (int r = 0; r < 8; ++r) sm->gg[r][n] = tf32r(tanh_acc(v[r] + b));
        }
        __syncthreads();

        // -------- dec2: y = g @ dw2 + db2   K=512 (split 8), N=8
        {
            int kg  = tid >> 6;       // 8 k-groups of 64
            int idx = tid & 63;
            int n   = idx & 7;        // lanes share gg address (broadcast)
            int r   = idx >> 3;
            float acc = 0.f;
            int kbase = kg << 6;
            #pragma unroll 8
            for (int kk = 0; kk < 64; ++kk) {
                int k = kbase + kk;
                acc = fmaf(sm->gg[r][k], rw_dw2[k * NOUT + n], acc);
            }
            sm->redF[tid] = acc;
        }
        __syncthreads();
        if (tid < 64) {
            int n = tid & 7, r = tid >> 3;
            float y = db2[n];
            #pragma unroll
            for (int j = 0; j < 8; ++j) y += sm->redF[(j << 6) + tid];
            if (n == f0) y = sm->uS[r][0];
            if (n == f1) y = sm->uS[r][1];
            sm->yS[r][n] = y;
            // output layout (NO, B, T): out[n][b][step]
            out[(size_t)n * BB * TOUTN + (size_t)(b0 + r) * TOUTN + (i - LBK)] = y;
        }
        __syncthreads();

        // -------- window shift: win[:,0:2] = win[:,1:3]; win[:,2] = y
        {
            float tmp[NOUT];
            int r = 0, t = 0;
            if (tid < RR * LBK) {
                r = tid / LBK; t = tid % LBK;
                #pragma unroll
                for (int c = 0; c < NOUT; ++c) {
                    if (t < LBK - 1) tmp[c] = sm->win[r][t + 1][c];
                    else             tmp[c] = sm->yS[r][c];
                }
            }
            __syncthreads();
            if (tid < RR * LBK) {
                #pragma unroll
                for (int c = 0; c < NOUT; ++c) sm->win[r][t][c] = tmp[c];
            }
        }
        __syncthreads();
    }
}

extern "C" void kernel_launch(void* const* d_in, const int* in_sizes, int n_in,
                              void* d_out, int out_size) {
    const float* inp = (const float*)d_in[0];
    const float* g1  = (const float*)d_in[1];
    const float* be1 = (const float*)d_in[2];
    const float* ew1 = (const float*)d_in[3];
    const float* eb1 = (const float*)d_in[4];
    const float* ew2 = (const float*)d_in[5];
    const float* eb2 = (const float*)d_in[6];
    const float* uw  = (const float*)d_in[7];
    const float* ub  = (const float*)d_in[8];
    const float* g2  = (const float*)d_in[9];
    const float* be2 = (const float*)d_in[10];
    const float* bw  = (const float*)d_in[11];
    const float* dw1 = (const float*)d_in[12];
    const float* db1 = (const float*)d_in[13];
    const float* dw2 = (const float*)d_in[14];
    const float* db2 = (const float*)d_in[15];
    const int*  fixp = (const int*)d_in[16];
    float* out = (float*)d_out;

    // Pre-round all weights to TF32 into device globals (graph-capturable,
    // deterministic, allocation-free).
    round_weights_kernel<<<192, 512>>>(ew1, ew2, uw, bw, dw1, dw2);

    cudaFuncSetAttribute(dps_kernel, cudaFuncAttributeMaxDynamicSharedMemorySize,
                         (int)sizeof(SmemT));
    dps_kernel<<<NBLK, NT, sizeof(SmemT)>>>(inp, g1, be1, eb1, eb2,
                                            ub, g2, be2, db1, db2, fixp, out);
}

// round 5
// speedup vs baseline: 1.2390x; 1.2390x over previous
#include <cuda_runtime.h>

// Problem constants (shapes fixed by the dataset)
#define BB    1024          // batch
#define SSEQ  2048          // sequence length
#define FFEAT 9             // input features (NO+1)
#define NOUT  8             // output channels
#define LBK   3             // lookback
#define DD    11            // NO+3 (ln1 width)
#define UU    256           // hidden U
#define H1N   512           // 2U
#define TOUTN 2044          // S-1-LBK output steps
#define RR    8             // batch rows per block
#define NT    512           // threads per block
#define NBLK  128           // BB / RR
#define LN_EPS 1e-3f

typedef unsigned long long u64;

// ---- packed fp32x2 helpers (Blackwell f32x2 pipe: 2 MACs per FFMA issue) ----
__device__ __forceinline__ u64 pack2(float lo, float hi) {
    u64 r; asm("mov.b64 %0, {%1,%2};" : "=l"(r) : "f"(lo), "f"(hi)); return r;
}
__device__ __forceinline__ void unpack2(u64 v, float& lo, float& hi) {
    asm("mov.b64 {%0,%1}, %2;" : "=f"(lo), "=f"(hi) : "l"(v));
}
__device__ __forceinline__ void fma2(u64& d, u64 a, u64 b) {
    asm("fma.rn.f32x2 %0, %1, %2, %0;" : "+l"(d) : "l"(a), "l"(b));
}
__device__ __forceinline__ u64 add2(u64 a, u64 b) {
    u64 r; asm("add.rn.f32x2 %0, %1, %2;" : "=l"(r) : "l"(a), "l"(b)); return r;
}

// ---- accurate math, immune to fast-math lowering ----------------------------
__device__ __forceinline__ float rcp_acc(float d) {
    float r0; asm("rcp.approx.f32 %0, %1;" : "=f"(r0) : "f"(d));
    float e = fmaf(-d, r0, 1.0f);
    return fmaf(r0, e, r0);
}

__device__ __forceinline__ float rsqrt_acc(float a) {
    float r; asm("rsqrt.approx.f32 %0, %1;" : "=f"(r) : "f"(a));
    float h = 0.5f * a;
    float e = fmaf(-h, r * r, 0.5f);
    return fmaf(r, e, r);
}

__device__ __forceinline__ float tanh_acc(float x) {
    float ax = fabsf(x);
    if (ax < 0.25f) {
        float x2 = x * x;
        float p = fmaf(x2, 2.1869489e-2f, -5.3968254e-2f);
        p = fmaf(x2, p, 1.3333334e-1f);
        p = fmaf(x2, p, -3.3333334e-1f);
        return fmaf(x * x2, p, x);
    }
    if (ax > 9.1f) return copysignf(1.0f, x);
    float t = ax * 2.88539008177793f;
    float n = rintf(t);
    float f = t - n;
    float p = fmaf(f, 1.5252734e-5f, 1.5403530e-4f);
    p = fmaf(f, p, 1.3333558e-3f);
    p = fmaf(f, p, 9.6181292e-3f);
    p = fmaf(f, p, 5.5504109e-2f);
    p = fmaf(f, p, 2.4022651e-1f);
    p = fmaf(f, p, 6.9314718e-1f);
    p = fmaf(f, p, 1.0f);
    float sc = __int_as_float(((int)n + 127) << 23);
    float q = p * sc;
    float r = rcp_acc(q + 1.0f);
    return copysignf(fmaf(-2.0f, r, 1.0f), x);
}

// Shared memory. Transposed activation arrays [feature][8 rows] give broadcast
// LDS.128 in the GEMV k-loops. redBig is the k-split reduction scratch, laid
// out [j][split][cg] so partial stores/loads are lane-consecutive (no bank
// conflicts).
struct __align__(16) SmemT {
    float4 xT[LBK * DD][2];     // x33 transposed  [k][r0..3],[r4..7]
    float4 h1T[H1N][2];         // tanh(enc1) transposed
    float4 hT[UU][2];           // enc2 out transposed
    float4 combT[UU + 1][2];    // [st, ect] transposed (dec1 operand)
    u64    redBig[16 * 7 * 64]; // split-K partial accs (56KB, reused per layer)
    float  hh[RR][UU + 8];      // enc2 out row-major (beta dot)
    float  ss[RR][UU + 8];      // upd out row-major (LN2 input)
    float  gg[RR][H1N + 8];     // dec1 pre/post-tanh row-major (dec2 input)
    float  redF[NT];            // dec2 reduction scratch
    float  win[RR][LBK][NOUT];  // rolling window
    float  yS[RR][NOUT];        // current step output
    float  uS[RR][2];           // forced update values
};

__global__ __launch_bounds__(NT, 1)
void dps_kernel(const float* __restrict__ inp,
                const float* __restrict__ g1,  const float* __restrict__ be1,
                const float* __restrict__ ew1, const float* __restrict__ eb1,
                const float* __restrict__ ew2, const float* __restrict__ eb2,
                const float* __restrict__ uw,  const float* __restrict__ ub,
                const float* __restrict__ g2,  const float* __restrict__ be2,
                const float* __restrict__ bw,
                const float* __restrict__ dw1, const float* __restrict__ db1,
                const float* __restrict__ dw2, const float* __restrict__ db2,
                const int* __restrict__ fixp,
                float* __restrict__ out)
{
    extern __shared__ char smraw[];
    SmemT* sm = reinterpret_cast<SmemT*>(smraw);
    const int tid = threadIdx.x;
    const int b0  = blockIdx.x * RR;

    const int f0 = fixp[0];
    const int f1 = fixp[1];

    // init rolling window: win = inputs[:, 0:3, 1:9]
    for (int idx = tid; idx < RR * LBK * NOUT; idx += NT) {
        int r = idx / (LBK * NOUT);
        int rem = idx % (LBK * NOUT);
        int t = rem / NOUT, c = rem % NOUT;
        sm->win[r][t][c] = inp[(size_t)(b0 + r) * SSEQ * FFEAT + t * FFEAT + 1 + c];
    }
    __syncthreads();

    float* xTf    = reinterpret_cast<float*>(sm->xT);
    float* combTf = reinterpret_cast<float*>(sm->combT);

    for (int i = LBK; i <= SSEQ - 2; ++i) {
        // -------- phase 0: build x (lc ++ window), LN1, write transposed
        if (tid < RR * LBK) {
            int r = tid / LBK, t = tid % LBK;
            int tp = i - LBK + t;
            const float* rowp = inp + (size_t)(b0 + r) * SSEQ * FFEAT;
            float L  = rowp[tp * FFEAT];
            float Lm = (tp > 0) ? rowp[(tp - 1) * FFEAT] : 0.0f;
            float v[DD];
            v[0] = L;                               // loading
            v[1] = L;                               // cumsum over size-1 axis == loading
            v[2] = (tp > 0) ? (L - Lm) : 0.0f;      // diff; padded to zero at t'=0
            #pragma unroll
            for (int c = 0; c < NOUT; ++c) v[3 + c] = sm->win[r][t][c];
            float s = 0.f;
            #pragma unroll
            for (int j = 0; j < DD; ++j) s += v[j];
            float m = s * (1.0f / DD);
            float q = 0.f;
            #pragma unroll
            for (int j = 0; j < DD; ++j) { float d = v[j] - m; q = fmaf(d, d, q); }
            float invs = rsqrt_acc(q * (1.0f / DD) + LN_EPS);
            #pragma unroll
            for (int j = 0; j < DD; ++j) {
                int k = t * DD + j;
                xTf[k * 8 + r] = fmaf((v[j] - m) * invs, g1[j], be1[j]);
            }
        } else if (tid >= 32 && tid < 32 + RR * 2) {
            int qq = tid - 32;
            int r = qq >> 1, j = qq & 1;
            int ch = 1 + (j ? f1 : f0);
            sm->uS[r][j] = inp[(size_t)(b0 + r) * SSEQ * FFEAT + (size_t)(i + 1) * FFEAT + ch];
        }
        __syncthreads();

        // -------- L1: h1 = tanh(x33 @ ew1 + eb1)   K=33, N=512 (1 col/thread)
        {
            const int n = tid;
            u64 a0 = 0, a1 = 0, a2 = 0, a3 = 0;
            #pragma unroll 3
            for (int k = 0; k < LBK * DD; ++k) {
                float w = ew1[k * H1N + n];
                u64 ww = pack2(w, w);
                ulonglong2 x01 = *reinterpret_cast<const ulonglong2*>(&sm->xT[k][0]);
                ulonglong2 x23 = *reinterpret_cast<const ulonglong2*>(&sm->xT[k][1]);
                fma2(a0, x01.x, ww); fma2(a1, x01.y, ww);
                fma2(a2, x23.x, ww); fma2(a3, x23.y, ww);
            }
            float v[8];
            unpack2(a0, v[0], v[1]); unpack2(a1, v[2], v[3]);
            unpack2(a2, v[4], v[5]); unpack2(a3, v[6], v[7]);
            float b = eb1[n];
            float4 o0, o1;
            o0.x = tanh_acc(v[0] + b); o0.y = tanh_acc(v[1] + b);
            o0.z = tanh_acc(v[2] + b); o0.w = tanh_acc(v[3] + b);
            o1.x = tanh_acc(v[4] + b); o1.y = tanh_acc(v[5] + b);
            o1.z = tanh_acc(v[6] + b); o1.w = tanh_acc(v[7] + b);
            sm->h1T[n][0] = o0; sm->h1T[n][1] = o1;
        }
        __syncthreads();

        // -------- L2: h = h1 @ ew2 + eb2   K=512, N=256
        // 4 cols/thread (strided), 8-way K split across warp pairs.
        {
            const int cg = tid & 63;        // column group: cols {cg, cg+64, cg+128, cg+192}
            const int s  = tid >> 6;        // k-split 0..7, uniform per warp
            u64 acc[16];
            #pragma unroll
            for (int j = 0; j < 16; ++j) acc[j] = 0;
            const float*  wp = ew2 + ((s << 6) * UU + cg);
            const ulonglong2* xp = reinterpret_cast<const ulonglong2*>(&sm->h1T[s << 6][0]);
            #pragma unroll 4
            for (int kk = 0; kk < 64; ++kk) {
                float w0 = wp[0], w1 = wp[64], w2 = wp[128], w3 = wp[192];
                ulonglong2 x01 = xp[0];
                ulonglong2 x23 = xp[1];
                u64 W;
                W = pack2(w0, w0); fma2(acc[0], x01.x, W); fma2(acc[1], x01.y, W); fma2(acc[2], x23.x, W); fma2(acc[3], x23.y, W);
                W = pack2(w1, w1); fma2(acc[4], x01.x, W); fma2(acc[5], x01.y, W); fma2(acc[6], x23.x, W); fma2(acc[7], x23.y, W);
                W = pack2(w2, w2); fma2(acc[8], x01.x, W); fma2(acc[9], x01.y, W); fma2(acc[10], x23.x, W); fma2(acc[11], x23.y, W);
                W = pack2(w3, w3); fma2(acc[12], x01.x, W); fma2(acc[13], x01.y, W); fma2(acc[14], x23.x, W); fma2(acc[15], x23.y, W);
                wp += UU; xp += 2;
            }
            if (s) {
                #pragma unroll
                for (int j = 0; j < 16; ++j)
                    sm->redBig[(j * 7 + (s - 1)) * 64 + cg] = acc[j];
            }
            __syncthreads();
            if (s == 0) {
                #pragma unroll
                for (int j = 0; j < 16; ++j) {
                    #pragma unroll
                    for (int t7 = 0; t7 < 7; ++t7)
                        acc[j] = add2(acc[j], sm->redBig[(j * 7 + t7) * 64 + cg]);
                }
                #pragma unroll
                for (int c = 0; c < 4; ++c) {
                    int n = cg + (c << 6);
                    float b = eb2[n];
                    float v[8];
                    unpack2(acc[c*4+0], v[0], v[1]); unpack2(acc[c*4+1], v[2], v[3]);
                    unpack2(acc[c*4+2], v[4], v[5]); unpack2(acc[c*4+3], v[6], v[7]);
                    #pragma unroll
                    for (int r = 0; r < 8; ++r) v[r] += b;
                    sm->hT[n][0] = make_float4(v[0], v[1], v[2], v[3]);
                    sm->hT[n][1] = make_float4(v[4], v[5], v[6], v[7]);
                    #pragma unroll
                    for (int r = 0; r < 8; ++r) sm->hh[r][n] = v[r];
                }
            }
        }
        __syncthreads();

        // -------- L3: s = h @ uw + ub   K=256, N=256  (4 cols/thread, 8 splits)
        {
            const int cg = tid & 63;
            const int s  = tid >> 6;
            u64 acc[16];
            #pragma unroll
            for (int j = 0; j < 16; ++j) acc[j] = 0;
            const float* wp = uw + ((s << 5) * UU + cg);
            const ulonglong2* xp = reinterpret_cast<const ulonglong2*>(&sm->hT[s << 5][0]);
            #pragma unroll 4
            for (int kk = 0; kk < 32; ++kk) {
                float w0 = wp[0], w1 = wp[64], w2 = wp[128], w3 = wp[192];
                ulonglong2 x01 = xp[0];
                ulonglong2 x23 = xp[1];
                u64 W;
                W = pack2(w0, w0); fma2(acc[0], x01.x, W); fma2(acc[1], x01.y, W); fma2(acc[2], x23.x, W); fma2(acc[3], x23.y, W);
                W = pack2(w1, w1); fma2(acc[4], x01.x, W); fma2(acc[5], x01.y, W); fma2(acc[6], x23.x, W); fma2(acc[7], x23.y, W);
                W = pack2(w2, w2); fma2(acc[8], x01.x, W); fma2(acc[9], x01.y, W); fma2(acc[10], x23.x, W); fma2(acc[11], x23.y, W);
                W = pack2(w3, w3); fma2(acc[12], x01.x, W); fma2(acc[13], x01.y, W); fma2(acc[14], x23.x, W); fma2(acc[15], x23.y, W);
                wp += UU; xp += 2;
            }
            if (s) {
                #pragma unroll
                for (int j = 0; j < 16; ++j)
                    sm->redBig[(j * 7 + (s - 1)) * 64 + cg] = acc[j];
            }
            __syncthreads();
            if (s == 0) {
                #pragma unroll
                for (int j = 0; j < 16; ++j) {
                    #pragma unroll
                    for (int t7 = 0; t7 < 7; ++t7)
                        acc[j] = add2(acc[j], sm->redBig[(j * 7 + t7) * 64 + cg]);
                }
                #pragma unroll
                for (int c = 0; c < 4; ++c) {
                    int n = cg + (c << 6);
                    float b = ub[n];
                    float v[8];
                    unpack2(acc[c*4+0], v[0], v[1]); unpack2(acc[c*4+1], v[2], v[3]);
                    unpack2(acc[c*4+2], v[4], v[5]); unpack2(acc[c*4+3], v[6], v[7]);
                    #pragma unroll
                    for (int r = 0; r < 8; ++r) sm->ss[r][n] = v[r] + b;
                }
            }
        }
        __syncthreads();

        // -------- LN2 (two-pass variance) + ect -> combT (warp w handles row w)
        if (tid < 256) {
            int r = tid >> 5, lane = tid & 31;
            float s = 0.f, e = 0.f;
            float vv[8];
            #pragma unroll
            for (int j = 0; j < 8; ++j) {
                int n = lane + (j << 5);
                float v = sm->ss[r][n];
                vv[j] = v;
                s += v;
                e = fmaf(sm->hh[r][n], bw[n], e);
            }
            #pragma unroll
            for (int o = 16; o > 0; o >>= 1) {
                s += __shfl_xor_sync(0xffffffffu, s, o);
                e += __shfl_xor_sync(0xffffffffu, e, o);
            }
            float m = s * (1.0f / UU);
            float q = 0.f;
            #pragma unroll
            for (int j = 0; j < 8; ++j) { float d = vv[j] - m; q = fmaf(d, d, q); }
            #pragma unroll
            for (int o = 16; o > 0; o >>= 1)
                q += __shfl_xor_sync(0xffffffffu, q, o);
            float invs = rsqrt_acc(q * (1.0f / UU) + LN_EPS);
            #pragma unroll
            for (int j = 0; j < 8; ++j) {
                int n = lane + (j << 5);
                combTf[n * 8 + r] = fmaf((vv[j] - m) * invs, g2[n], be2[n]);
            }
            if (lane == 0) combTf[UU * 8 + r] = e;   // ect at comb index 256
        }
        __syncthreads();

        // -------- dec1: g = tanh(comb @ dw1 + db1)  K=257, N=512
        // 4 cols/thread (strided), 4-way K split (last split takes k=192..256).
        {
            const int cg = tid & 127;       // cols {cg, cg+128, cg+256, cg+384}
            const int s  = tid >> 7;        // k-split 0..3, uniform per warp
            u64 acc[16];
            #pragma unroll
            for (int j = 0; j < 16; ++j) acc[j] = 0;
            const int kcnt = (s == 3) ? 65 : 64;
            const float* wp = dw1 + ((s << 6) * H1N + cg);
            const ulonglong2* xp = reinterpret_cast<const ulonglong2*>(&sm->combT[s << 6][0]);
            #pragma unroll 4
            for (int kk = 0; kk < kcnt; ++kk) {
                float w0 = wp[0], w1 = wp[128], w2 = wp[256], w3 = wp[384];
                ulonglong2 x01 = xp[0];
                ulonglong2 x23 = xp[1];
                u64 W;
                W = pack2(w0, w0); fma2(acc[0], x01.x, W); fma2(acc[1], x01.y, W); fma2(acc[2], x23.x, W); fma2(acc[3], x23.y, W);
                W = pack2(w1, w1); fma2(acc[4], x01.x, W); fma2(acc[5], x01.y, W); fma2(acc[6], x23.x, W); fma2(acc[7], x23.y, W);
                W = pack2(w2, w2); fma2(acc[8], x01.x, W); fma2(acc[9], x01.y, W); fma2(acc[10], x23.x, W); fma2(acc[11], x23.y, W);
                W = pack2(w3, w3); fma2(acc[12], x01.x, W); fma2(acc[13], x01.y, W); fma2(acc[14], x23.x, W); fma2(acc[15], x23.y, W);
                wp += H1N; xp += 2;
            }
            if (s) {
                #pragma unroll
                for (int j = 0; j < 16; ++j)
                    sm->redBig[(j * 3 + (s - 1)) * 128 + cg] = acc[j];
            }
            __syncthreads();
            if (s == 0) {
                #pragma unroll
                for (int j = 0; j < 16; ++j) {
                    #pragma unroll
                    for (int t3 = 0; t3 < 3; ++t3)
                        acc[j] = add2(acc[j], sm->redBig[(j * 3 + t3) * 128 + cg]);
                }
                #pragma unroll
                for (int c = 0; c < 4; ++c) {
                    int n = cg + (c << 7);
                    float b = db1[n];
                    float v[8];
                    unpack2(acc[c*4+0], v[0], v[1]); unpack2(acc[c*4+1], v[2], v[3]);
                    unpack2(acc[c*4+2], v[4], v[5]); unpack2(acc[c*4+3], v[6], v[7]);
                    #pragma unroll
                    for (int r = 0; r < 8; ++r) sm->gg[r][n] = v[r] + b;  // raw (pre-tanh)
                }
            }
        }
        __syncthreads();

        // tanh pass over gg, balanced across all 512 threads (8 elems each)
        {
            int r  = tid >> 6;
            int n0 = (tid & 63) << 3;
            float4* gp = reinterpret_cast<float4*>(&sm->gg[r][n0]);
            float4 A = gp[0], B = gp[1];
            A.x = tanh_acc(A.x); A.y = tanh_acc(A.y); A.z = tanh_acc(A.z); A.w = tanh_acc(A.w);
            B.x = tanh_acc(B.x); B.y = tanh_acc(B.y); B.z = tanh_acc(B.z); B.w = tanh_acc(B.w);
            gp[0] = A; gp[1] = B;
        }
        __syncthreads();

        // -------- dec2: y = g @ dw2 + db2   K=512 (split 8), N=8
        {
            int kg  = tid >> 6;       // 8 k-groups of 64
            int idx = tid & 63;
            int n   = idx & 7;        // lanes share gg address (broadcast)
            int r   = idx >> 3;
            float acc = 0.f;
            int kbase = kg << 6;
            #pragma unroll 8
            for (int kk = 0; kk < 64; ++kk) {
                int k = kbase + kk;
                acc = fmaf(sm->gg[r][k], dw2[k * NOUT + n], acc);
            }
            sm->redF[tid] = acc;
        }
        __syncthreads();
        if (tid < 64) {
            int n = tid & 7, r = tid >> 3;
            float y = db2[n];
            #pragma unroll
            for (int j = 0; j < 8; ++j) y += sm->redF[(j << 6) + tid];
            if (n == f0) y = sm->uS[r][0];
            if (n == f1) y = sm->uS[r][1];
            sm->yS[r][n] = y;
            // output layout (NO, B, T): out[n][b][step]
            out[(size_t)n * BB * TOUTN + (size_t)(b0 + r) * TOUTN + (i - LBK)] = y;
        }
        __syncthreads();

        // -------- window shift: win[:,0:2] = win[:,1:3]; win[:,2] = y
        {
            float tmp[NOUT];
            int r = 0, t = 0;
            if (tid < RR * LBK) {
                r = tid / LBK; t = tid % LBK;
                #pragma unroll
                for (int c = 0; c < NOUT; ++c) {
                    if (t < LBK - 1) tmp[c] = sm->win[r][t + 1][c];
                    else             tmp[c] = sm->yS[r][c];
                }
            }
            __syncthreads();
            if (tid < RR * LBK) {
                #pragma unroll
                for (int c = 0; c < NOUT; ++c) sm->win[r][t][c] = tmp[c];
            }
        }
        __syncthreads();
    }
}

extern "C" void kernel_launch(void* const* d_in, const int* in_sizes, int n_in,
                              void* d_out, int out_size) {
    const float* inp = (const float*)d_in[0];
    const float* g1  = (const float*)d_in[1];
    const float* be1 = (const float*)d_in[2];
    const float* ew1 = (const float*)d_in[3];
    const float* eb1 = (const float*)d_in[4];
    const float* ew2 = (const float*)d_in[5];
    const float* eb2 = (const float*)d_in[6];
    const float* uw  = (const float*)d_in[7];
    const float* ub  = (const float*)d_in[8];
    const float* g2  = (const float*)d_in[9];
    const float* be2 = (const float*)d_in[10];
    const float* bw  = (const float*)d_in[11];
    const float* dw1 = (const float*)d_in[12];
    const float* db1 = (const float*)d_in[13];
    const float* dw2 = (const float*)d_in[14];
    const float* db2 = (const float*)d_in[15];
    const int*  fixp = (const int*)d_in[16];
    float* out = (float*)d_out;

    cudaFuncSetAttribute(dps_kernel, cudaFuncAttributeMaxDynamicSharedMemorySize,
                         (int)sizeof(SmemT));
    dps_kernel<<<NBLK, NT, sizeof(SmemT)>>>(inp, g1, be1, ew1, eb1, ew2, eb2,
                                            uw, ub, g2, be2, bw, dw1, db1,
                                            dw2, db2, fixp, out);
}

// round 6
// speedup vs baseline: 1.4786x; 1.1934x over previous
#include <cuda_runtime.h>

// Problem constants (shapes fixed by the dataset)
#define BB    1024
#define SSEQ  2048
#define FFEAT 9
#define NOUT  8
#define LBK   3
#define DD    11
#define UU    256
#define H1N   512
#define TOUTN 2044
#define RR    8
#define NT    512
#define NBLK  128
#define LN_EPS 1e-3f

typedef unsigned long long u64;

// ---- packed fp32x2 helpers --------------------------------------------------
__device__ __forceinline__ u64 pack2(float lo, float hi) {
    u64 r; asm("mov.b64 %0, {%1,%2};" : "=l"(r) : "f"(lo), "f"(hi)); return r;
}
__device__ __forceinline__ void unpack2(u64 v, float& lo, float& hi) {
    asm("mov.b64 {%0,%1}, %2;" : "=f"(lo), "=f"(hi) : "l"(v));
}
__device__ __forceinline__ void fma2(u64& d, u64 a, u64 b) {
    asm("fma.rn.f32x2 %0, %1, %2, %0;" : "+l"(d) : "l"(a), "l"(b));
}
__device__ __forceinline__ u64 add2(u64 a, u64 b) {
    u64 r; asm("add.rn.f32x2 %0, %1, %2;" : "=l"(r) : "l"(a), "l"(b)); return r;
}

// ---- accurate math ----------------------------------------------------------
__device__ __forceinline__ float rcp_acc(float d) {
    float r0; asm("rcp.approx.f32 %0, %1;" : "=f"(r0) : "f"(d));
    float e = fmaf(-d, r0, 1.0f);
    return fmaf(r0, e, r0);
}
__device__ __forceinline__ float rsqrt_acc(float a) {
    float r; asm("rsqrt.approx.f32 %0, %1;" : "=f"(r) : "f"(a));
    float h = 0.5f * a;
    float e = fmaf(-h, r * r, 0.5f);
    return fmaf(r, e, r);
}
__device__ __forceinline__ float tanh_acc(float x) {
    float ax = fabsf(x);
    if (ax < 0.25f) {
        float x2 = x * x;
        float p = fmaf(x2, 2.1869489e-2f, -5.3968254e-2f);
        p = fmaf(x2, p, 1.3333334e-1f);
        p = fmaf(x2, p, -3.3333334e-1f);
        return fmaf(x * x2, p, x);
    }
    if (ax > 9.1f) return copysignf(1.0f, x);
    float t = ax * 2.88539008177793f;
    float n = rintf(t);
    float f = t - n;
    float p = fmaf(f, 1.5252734e-5f, 1.5403530e-4f);
    p = fmaf(f, p, 1.3333558e-3f);
    p = fmaf(f, p, 9.6181292e-3f);
    p = fmaf(f, p, 5.5504109e-2f);
    p = fmaf(f, p, 2.4022651e-1f);
    p = fmaf(f, p, 6.9314718e-1f);
    p = fmaf(f, p, 1.0f);
    float sc = __int_as_float(((int)n + 127) << 23);
    float q = p * sc;
    float r = rcp_acc(q + 1.0f);
    return copysignf(fmaf(-2.0f, r, 1.0f), x);
}

// Shared memory. h1T padded to 48B/row so L1's transposed stores are
// bank-conflict-free. red is the all-splits partial buffer, groups padded to
// 18 u64 so both STS.128 stores and reduction loads avoid conflicts.
struct __align__(16) SmemT {
    float4 xT[LBK * DD][2];     // x33 transposed [k][r0-3],[r4-7]
    float4 h1T[H1N][3];         // tanh(enc1) transposed, 48B stride ([2] pad)
    float4 hT[UU][2];           // enc2 out transposed
    float4 combT[UU + 1][2];    // [st, ect] transposed
    u64    red[512 * 18];       // split-K partials: group=(s*G+cg), 16 used + 2 pad
    float  hh[RR][UU + 8];      // enc2 out row-major
    float  ss[RR][UU + 8];      // upd out row-major
    float  gg[RR][H1N + 8];     // tanh(dec1) row-major
    float  sdw2[H1N][NOUT];     // dec2 weights cached
    float  redF[NT];            // dec2 reduction scratch
    float  win[RR][LBK][NOUT];  // rolling window
    float  yS[RR][NOUT];        // current step output
    float  uS[RR][2];           // forced update values
};

__global__ __launch_bounds__(NT, 1)
void dps_kernel(const float* __restrict__ inp,
                const float* __restrict__ g1,  const float* __restrict__ be1,
                const float* __restrict__ ew1, const float* __restrict__ eb1,
                const float* __restrict__ ew2, const float* __restrict__ eb2,
                const float* __restrict__ uw,  const float* __restrict__ ub,
                const float* __restrict__ g2,  const float* __restrict__ be2,
                const float* __restrict__ bw,
                const float* __restrict__ dw1, const float* __restrict__ db1,
                const float* __restrict__ dw2, const float* __restrict__ db2,
                const int* __restrict__ fixp,
                float* __restrict__ out)
{
    extern __shared__ char smraw[];
    SmemT* sm = reinterpret_cast<SmemT*>(smraw);
    const int tid = threadIdx.x;
    const int b0  = blockIdx.x * RR;

    const int f0 = fixp[0];
    const int f1 = fixp[1];

    // init rolling window + dec2 weight cache
    for (int idx = tid; idx < RR * LBK * NOUT; idx += NT) {
        int r = idx / (LBK * NOUT);
        int rem = idx % (LBK * NOUT);
        int t = rem / NOUT, c = rem % NOUT;
        sm->win[r][t][c] = inp[(size_t)(b0 + r) * SSEQ * FFEAT + t * FFEAT + 1 + c];
    }
    {
        float* sd = &sm->sdw2[0][0];
        #pragma unroll
        for (int j = 0; j < 8; ++j) sd[j * NT + tid] = dw2[j * NT + tid];
    }
    __syncthreads();

    float* xTf    = reinterpret_cast<float*>(sm->xT);
    float* combTf = reinterpret_cast<float*>(sm->combT);
    u64*   hTu    = reinterpret_cast<u64*>(sm->hT);

    // thread->tile mappings
    const int cg6 = tid & 63,  s6 = tid >> 6;   // L2/L3: 64 col-groups x 8 splits
    const int cg7 = tid & 127, s7 = tid >> 7;   // dec1: 128 col-groups x 4 splits

    // Step-invariant first-iteration weights, register-resident for the whole
    // kernel: kills the phase-start LDG latency on every step.
    const float  w1first = __ldg(&ew1[tid]);
    const float4 w2first = __ldg((const float4*)ew2 + (size_t)(s6 << 6) * 64 + cg6);
    const float4 w3first = __ldg((const float4*)uw  + (size_t)(s6 << 5) * 64 + cg6);
    const float4 wdfirst = __ldg((const float4*)dw1 + (size_t)(s7 << 6) * 128 + cg7);

    for (int i = LBK; i <= SSEQ - 2; ++i) {
        // ---- phase 0 (warps 0-1 only; others run ahead to the barrier) ----
        // named barrier orders prev-iter dec2-final (warps 0,1) with this read
        if (tid < 64) asm volatile("bar.sync 1, 64;" ::: "memory");
        if (tid < RR * LBK) {
            int r = tid / LBK, t = tid % LBK;
            float wv[NOUT];
            if (i == LBK) {
                #pragma unroll
                for (int c = 0; c < NOUT; ++c) wv[c] = sm->win[r][t][c];
            } else {
                #pragma unroll
                for (int c = 0; c < NOUT; ++c)
                    wv[c] = (t < LBK - 1) ? sm->win[r][t + 1][c] : sm->yS[r][c];
            }
            __syncwarp(0x00FFFFFFu);
            if (i > LBK) {
                #pragma unroll
                for (int c = 0; c < NOUT; ++c) sm->win[r][t][c] = wv[c];
            }
            int tp = i - LBK + t;
            const float* rowp = inp + (size_t)(b0 + r) * SSEQ * FFEAT;
            float L  = rowp[tp * FFEAT];
            float Lm = (tp > 0) ? rowp[(tp - 1) * FFEAT] : 0.0f;
            float v[DD];
            v[0] = L;
            v[1] = L;                               // cumsum over size-1 axis
            v[2] = (tp > 0) ? (L - Lm) : 0.0f;      // diff padded to 0 at t'=0
            #pragma unroll
            for (int c = 0; c < NOUT; ++c) v[3 + c] = wv[c];
            float s = 0.f;
            #pragma unroll
            for (int j = 0; j < DD; ++j) s += v[j];
            float m = s * (1.0f / DD);
            float q = 0.f;
            #pragma unroll
            for (int j = 0; j < DD; ++j) { float d = v[j] - m; q = fmaf(d, d, q); }
            float invs = rsqrt_acc(q * (1.0f / DD) + LN_EPS);
            #pragma unroll
            for (int j = 0; j < DD; ++j) {
                int k = t * DD + j;
                xTf[k * 8 + r] = fmaf((v[j] - m) * invs, g1[j], be1[j]);
            }
        } else if (tid >= 32 && tid < 32 + RR * 2) {
            int qq = tid - 32;
            int r = qq >> 1, j = qq & 1;
            int ch = 1 + (j ? f1 : f0);
            sm->uS[r][j] = inp[(size_t)(b0 + r) * SSEQ * FFEAT + (size_t)(i + 1) * FFEAT + ch];
        }
        __syncthreads();   // S2: xT ready

        // ---- L1: h1 = tanh(x33 @ ew1 + eb1)  K=33, N=512 (1 col/thread) ----
        {
            const int n = tid;
            u64 a0 = 0, a1 = 0, a2 = 0, a3 = 0;
            float w = w1first;
            const float* wp1 = ew1 + H1N + n;
            #pragma unroll
            for (int k = 0; k < LBK * DD; ++k) {
                float wn = 0.0f;
                if (k < LBK * DD - 1) { wn = *wp1; wp1 += H1N; }
                u64 ww = pack2(w, w);
                ulonglong2 x01 = *reinterpret_cast<const ulonglong2*>(&sm->xT[k][0]);
                ulonglong2 x23 = *reinterpret_cast<const ulonglong2*>(&sm->xT[k][1]);
                fma2(a0, x01.x, ww); fma2(a1, x01.y, ww);
                fma2(a2, x23.x, ww); fma2(a3, x23.y, ww);
                w = wn;
            }
            float v[8];
            unpack2(a0, v[0], v[1]); unpack2(a1, v[2], v[3]);
            unpack2(a2, v[4], v[5]); unpack2(a3, v[6], v[7]);
            float b = eb1[n];
            float4 o0, o1;
            o0.x = tanh_acc(v[0] + b); o0.y = tanh_acc(v[1] + b);
            o0.z = tanh_acc(v[2] + b); o0.w = tanh_acc(v[3] + b);
            o1.x = tanh_acc(v[4] + b); o1.y = tanh_acc(v[5] + b);
            o1.z = tanh_acc(v[6] + b); o1.w = tanh_acc(v[7] + b);
            sm->h1T[n][0] = o0; sm->h1T[n][1] = o1;
        }
        __syncthreads();   // S3: h1T ready

        // ---- L2 main: h = h1 @ ew2, K=512 (8 splits), 4 consecutive cols/thread
        {
            u64 acc[16];
            #pragma unroll
            for (int j = 0; j < 16; ++j) acc[j] = 0;
            const float4* wp = (const float4*)ew2 + (size_t)((s6 << 6) + 1) * 64 + cg6;
            const ulonglong2* xp = reinterpret_cast<const ulonglong2*>(&sm->h1T[s6 << 6][0]);
            float4 w = w2first;
            #pragma unroll 3
            for (int kk = 0; kk < 63; ++kk) {
                float4 wn = *wp; wp += 64;
                ulonglong2 x01 = xp[0], x23 = xp[1]; xp += 3;
                u64 W;
                W = pack2(w.x, w.x); fma2(acc[0], x01.x, W); fma2(acc[1], x01.y, W); fma2(acc[2], x23.x, W); fma2(acc[3], x23.y, W);
                W = pack2(w.y, w.y); fma2(acc[4], x01.x, W); fma2(acc[5], x01.y, W); fma2(acc[6], x23.x, W); fma2(acc[7], x23.y, W);
                W = pack2(w.z, w.z); fma2(acc[8], x01.x, W); fma2(acc[9], x01.y, W); fma2(acc[10], x23.x, W); fma2(acc[11], x23.y, W);
                W = pack2(w.w, w.w); fma2(acc[12], x01.x, W); fma2(acc[13], x01.y, W); fma2(acc[14], x23.x, W); fma2(acc[15], x23.y, W);
                w = wn;
            }
            {   // final k
                ulonglong2 x01 = xp[0], x23 = xp[1];
                u64 W;
                W = pack2(w.x, w.x); fma2(acc[0], x01.x, W); fma2(acc[1], x01.y, W); fma2(acc[2], x23.x, W); fma2(acc[3], x23.y, W);
                W = pack2(w.y, w.y); fma2(acc[4], x01.x, W); fma2(acc[5], x01.y, W); fma2(acc[6], x23.x, W); fma2(acc[7], x23.y, W);
                W = pack2(w.z, w.z); fma2(acc[8], x01.x, W); fma2(acc[9], x01.y, W); fma2(acc[10], x23.x, W); fma2(acc[11], x23.y, W);
                W = pack2(w.w, w.w); fma2(acc[12], x01.x, W); fma2(acc[13], x01.y, W); fma2(acc[14], x23.x, W); fma2(acc[15], x23.y, W);
            }
            ulonglong2* rb = reinterpret_cast<ulonglong2*>(sm->red + ((s6 << 6) + cg6) * 18);
            #pragma unroll
            for (int j = 0; j < 8; ++j) rb[j] = make_ulonglong2(acc[2 * j], acc[2 * j + 1]);
        }
        __syncthreads();   // S4: partials stored

        // ---- L2 reduction (all 512 threads): bias, write hT + hh ----
        {
            #pragma unroll
            for (int rep = 0; rep < 2; ++rep) {
                int o = tid + (rep << 9);
                int cgo = o >> 4, idx = o & 15;
                const u64* rp = sm->red + cgo * 18 + idx;
                u64 a = rp[0];
                #pragma unroll
                for (int sI = 1; sI < 8; ++sI) a = add2(a, rp[sI * 1152]);
                int c = idx >> 2, q = idx & 3;
                int n = (cgo << 2) + c;
                float lo, hi; unpack2(a, lo, hi);
                float b = __ldg(&eb2[n]); lo += b; hi += b;
                hTu[(n << 2) + q] = pack2(lo, hi);
                sm->hh[2 * q][n] = lo; sm->hh[2 * q + 1][n] = hi;
            }
        }
        __syncthreads();   // S5: hT/hh ready, red free

        // ---- L3 main: s = h @ uw, K=256 (8 splits) ----
        {
            u64 acc[16];
            #pragma unroll
            for (int j = 0; j < 16; ++j) acc[j] = 0;
            const float4* wp = (const float4*)uw + (size_t)((s6 << 5) + 1) * 64 + cg6;
            const ulonglong2* xp = reinterpret_cast<const ulonglong2*>(&sm->hT[s6 << 5][0]);
            float4 w = w3first;
            #pragma unroll 3
            for (int kk = 0; kk < 31; ++kk) {
                float4 wn = *wp; wp += 64;
                ulonglong2 x01 = xp[0], x23 = xp[1]; xp += 2;
                u64 W;
                W = pack2(w.x, w.x); fma2(acc[0], x01.x, W); fma2(acc[1], x01.y, W); fma2(acc[2], x23.x, W); fma2(acc[3], x23.y, W);
                W = pack2(w.y, w.y); fma2(acc[4], x01.x, W); fma2(acc[5], x01.y, W); fma2(acc[6], x23.x, W); fma2(acc[7], x23.y, W);
                W = pack2(w.z, w.z); fma2(acc[8], x01.x, W); fma2(acc[9], x01.y, W); fma2(acc[10], x23.x, W); fma2(acc[11], x23.y, W);
                W = pack2(w.w, w.w); fma2(acc[12], x01.x, W); fma2(acc[13], x01.y, W); fma2(acc[14], x23.x, W); fma2(acc[15], x23.y, W);
                w = wn;
            }
            {
                ulonglong2 x01 = xp[0], x23 = xp[1];
                u64 W;
                W = pack2(w.x, w.x); fma2(acc[0], x01.x, W); fma2(acc[1], x01.y, W); fma2(acc[2], x23.x, W); fma2(acc[3], x23.y, W);
                W = pack2(w.y, w.y); fma2(acc[4], x01.x, W); fma2(acc[5], x01.y, W); fma2(acc[6], x23.x, W); fma2(acc[7], x23.y, W);
                W = pack2(w.z, w.z); fma2(acc[8], x01.x, W); fma2(acc[9], x01.y, W); fma2(acc[10], x23.x, W); fma2(acc[11], x23.y, W);
                W = pack2(w.w, w.w); fma2(acc[12], x01.x, W); fma2(acc[13], x01.y, W); fma2(acc[14], x23.x, W); fma2(acc[15], x23.y, W);
            }
            ulonglong2* rb = reinterpret_cast<ulonglong2*>(sm->red + ((s6 << 6) + cg6) * 18);
            #pragma unroll
            for (int j = 0; j < 8; ++j) rb[j] = make_ulonglong2(acc[2 * j], acc[2 * j + 1]);
        }
        __syncthreads();   // S6

        // ---- L3 reduction: bias, write ss ----
        {
            #pragma unroll
            for (int rep = 0; rep < 2; ++rep) {
                int o = tid + (rep << 9);
                int cgo = o >> 4, idx = o & 15;
                const u64* rp = sm->red + cgo * 18 + idx;
                u64 a = rp[0];
                #pragma unroll
                for (int sI = 1; sI < 8; ++sI) a = add2(a, rp[sI * 1152]);
                int c = idx >> 2, q = idx & 3;
                int n = (cgo << 2) + c;
                float lo, hi; unpack2(a, lo, hi);
                float b = __ldg(&ub[n]); lo += b; hi += b;
                sm->ss[2 * q][n] = lo; sm->ss[2 * q + 1][n] = hi;
            }
        }
        __syncthreads();   // S7

        // ---- LN2 + ect -> combT (warp w handles row w) ----
        if (tid < 256) {
            int r = tid >> 5, lane = tid & 31;
            float s = 0.f, e = 0.f;
            float vv[8];
            #pragma unroll
            for (int j = 0; j < 8; ++j) {
                int n = lane + (j << 5);
                float v = sm->ss[r][n];
                vv[j] = v;
                s += v;
                e = fmaf(sm->hh[r][n], bw[n], e);
            }
            #pragma unroll
            for (int o = 16; o > 0; o >>= 1) {
                s += __shfl_xor_sync(0xffffffffu, s, o);
                e += __shfl_xor_sync(0xffffffffu, e, o);
            }
            float m = s * (1.0f / UU);
            float q = 0.f;
            #pragma unroll
            for (int j = 0; j < 8; ++j) { float d = vv[j] - m; q = fmaf(d, d, q); }
            #pragma unroll
            for (int o = 16; o > 0; o >>= 1)
                q += __shfl_xor_sync(0xffffffffu, q, o);
            float invs = rsqrt_acc(q * (1.0f / UU) + LN_EPS);
            #pragma unroll
            for (int j = 0; j < 8; ++j) {
                int n = lane + (j << 5);
                combTf[n * 8 + r] = fmaf((vv[j] - m) * invs, g2[n], be2[n]);
            }
            if (lane == 0) combTf[UU * 8 + r] = e;
        }
        __syncthreads();   // S8: combT ready

        // ---- dec1 main: comb @ dw1, K=257 (4 splits) ----
        {
            u64 acc[16];
            #pragma unroll
            for (int j = 0; j < 16; ++j) acc[j] = 0;
            const int kcnt = (s7 == 3) ? 65 : 64;
            const float4* wp = (const float4*)dw1 + (size_t)((s7 << 6) + 1) * 128 + cg7;
            const ulonglong2* xp = reinterpret_cast<const ulonglong2*>(&sm->combT[s7 << 6][0]);
            float4 w = wdfirst;
            #pragma unroll 3
            for (int kk = 0; kk < kcnt - 1; ++kk) {
                float4 wn = *wp; wp += 128;
                ulonglong2 x01 = xp[0], x23 = xp[1]; xp += 2;
                u64 W;
                W = pack2(w.x, w.x); fma2(acc[0], x01.x, W); fma2(acc[1], x01.y, W); fma2(acc[2], x23.x, W); fma2(acc[3], x23.y, W);
                W = pack2(w.y, w.y); fma2(acc[4], x01.x, W); fma2(acc[5], x01.y, W); fma2(acc[6], x23.x, W); fma2(acc[7], x23.y, W);
                W = pack2(w.z, w.z); fma2(acc[8], x01.x, W); fma2(acc[9], x01.y, W); fma2(acc[10], x23.x, W); fma2(acc[11], x23.y, W);
                W = pack2(w.w, w.w); fma2(acc[12], x01.x, W); fma2(acc[13], x01.y, W); fma2(acc[14], x23.x, W); fma2(acc[15], x23.y, W);
                w = wn;
            }
            {
                ulonglong2 x01 = xp[0], x23 = xp[1];
                u64 W;
                W = pack2(w.x, w.x); fma2(acc[0], x01.x, W); fma2(acc[1], x01.y, W); fma2(acc[2], x23.x, W); fma2(acc[3], x23.y, W);
                W = pack2(w.y, w.y); fma2(acc[4], x01.x, W); fma2(acc[5], x01.y, W); fma2(acc[6], x23.x, W); fma2(acc[7], x23.y, W);
                W = pack2(w.z, w.z); fma2(acc[8], x01.x, W); fma2(acc[9], x01.y, W); fma2(acc[10], x23.x, W); fma2(acc[11], x23.y, W);
                W = pack2(w.w, w.w); fma2(acc[12], x01.x, W); fma2(acc[13], x01.y, W); fma2(acc[14], x23.x, W); fma2(acc[15], x23.y, W);
            }
            ulonglong2* rb = reinterpret_cast<ulonglong2*>(sm->red + ((s7 << 7) + cg7) * 18);
            #pragma unroll
            for (int j = 0; j < 8; ++j) rb[j] = make_ulonglong2(acc[2 * j], acc[2 * j + 1]);
        }
        __syncthreads();   // S9

        // ---- dec1 reduction + bias + tanh -> gg ----
        {
            #pragma unroll
            for (int rep = 0; rep < 4; ++rep) {
                int o = tid + (rep << 9);
                int cgo = o >> 4, idx = o & 15;
                const u64* rp = sm->red + cgo * 18 + idx;
                u64 a = rp[0];
                #pragma unroll
                for (int sI = 1; sI < 4; ++sI) a = add2(a, rp[sI * 2304]);
                int c = idx >> 2, q = idx & 3;
                int n = (cgo << 2) + c;
                float lo, hi; unpack2(a, lo, hi);
                float b = __ldg(&db1[n]);
                sm->gg[2 * q][n]     = tanh_acc(lo + b);
                sm->gg[2 * q + 1][n] = tanh_acc(hi + b);
            }
        }
        __syncthreads();   // S10: gg ready

        // ---- dec2 partial: y = g @ dw2, K=512 split 8, N=8 ----
        {
            int kg  = tid >> 6;
            int idx = tid & 63;
            int n   = idx & 7;
            int r   = idx >> 3;
            float acc = 0.f;
            int kbase = kg << 6;
            #pragma unroll 8
            for (int kk = 0; kk < 64; ++kk) {
                int k = kbase + kk;
                acc = fmaf(sm->gg[r][k], sm->sdw2[k][n], acc);
            }
            sm->redF[tid] = acc;
        }
        __syncthreads();   // S11

        // ---- dec2 final + output (warps 0,1); loop-top bar#1 orders with phase0
        if (tid < 64) {
            int n = tid & 7, r = tid >> 3;
            float y = db2[n];
            #pragma unroll
            for (int j = 0; j < 8; ++j) y += sm->redF[(j << 6) + tid];
            if (n == f0) y = sm->uS[r][0];
            if (n == f1) y = sm->uS[r][1];
            sm->yS[r][n] = y;
            out[(size_t)n * BB * TOUTN + (size_t)(b0 + r) * TOUTN + (i - LBK)] = y;
        }
    }
}

extern "C" void kernel_launch(void* const* d_in, const int* in_sizes, int n_in,
                              void* d_out, int out_size) {
    const float* inp = (const float*)d_in[0];
    const float* g1  = (const float*)d_in[1];
    const float* be1 = (const float*)d_in[2];
    const float* ew1 = (const float*)d_in[3];
    const float* eb1 = (const float*)d_in[4];
    const float* ew2 = (const float*)d_in[5];
    const float* eb2 = (const float*)d_in[6];
    const float* uw  = (const float*)d_in[7];
    const float* ub  = (const float*)d_in[8];
    const float* g2  = (const float*)d_in[9];
    const float* be2 = (const float*)d_in[10];
    const float* bw  = (const float*)d_in[11];
    const float* dw1 = (const float*)d_in[12];
    const float* db1 = (const float*)d_in[13];
    const float* dw2 = (const float*)d_in[14];
    const float* db2 = (const float*)d_in[15];
    const int*  fixp = (const int*)d_in[16];
    float* out = (float*)d_out;

    cudaFuncSetAttribute(dps_kernel, cudaFuncAttributeMaxDynamicSharedMemorySize,
                         (int)sizeof(SmemT));
    dps_kernel<<<NBLK, NT, sizeof(SmemT)>>>(inp, g1, be1, ew1, eb1, ew2, eb2,
                                            uw, ub, g2, be2, bw, dw1, db1,
                                            dw2, db2, fixp, out);
}